// round 2
// baseline (speedup 1.0000x reference)
#include <cuda_runtime.h>

#define THREADS 256
#define TILE_E 64
#define EPAD 68

// shared-memory layout (float offsets)
#define OFF_W1   0          // 144*64 = 9216
#define OFF_W2   9216       // 64*64  = 4096
#define OFF_W3   13312      // 64
#define OFF_B1   13376
#define OFF_G1   13440
#define OFF_BE1  13504
#define OFF_B2   13568
#define OFF_G2   13632
#define OFF_BE2  13696
#define OFF_X    13764      // 144*EPAD = 9792 (16B aligned: 13764 % 4 == 0)
#define SMEM_FLOATS (13764 + 144*EPAD)   // 23556 floats = 94224 bytes

__global__ __launch_bounds__(THREADS, 2)
void edge_mlp_kernel(const float* __restrict__ nf,
                     const int* __restrict__ eidx,      // int32! (JAX x64 disabled)
                     const float* __restrict__ eattr,
                     const float* __restrict__ W1, const float* __restrict__ b1,
                     const float* __restrict__ g1, const float* __restrict__ be1,
                     const float* __restrict__ W2, const float* __restrict__ b2,
                     const float* __restrict__ g2, const float* __restrict__ be2,
                     const float* __restrict__ W3, const float* __restrict__ b3,
                     float* __restrict__ out, int E)
{
    extern __shared__ float smem[];
    float* w1s  = smem + OFF_W1;
    float* w2s  = smem + OFF_W2;
    float* w3s  = smem + OFF_W3;
    float* b1s  = smem + OFF_B1;
    float* g1s  = smem + OFF_G1;
    float* be1s = smem + OFF_BE1;
    float* b2s  = smem + OFF_B2;
    float* g2s  = smem + OFF_G2;
    float* be2s = smem + OFF_BE2;
    float* xs   = smem + OFF_X;          // [144][EPAD]  (x transposed: xs[k][e])
    float* hs   = xs;                    // reuse: [64][EPAD] row-major h
    float* x2s  = xs + 64 * EPAD;        // reuse: [64][EPAD] transposed h1

    const int t = threadIdx.x;

    // ---- load weights/params into smem (once per block) ----
    for (int i = t; i < 144 * 64; i += THREADS) w1s[i] = W1[i];
    for (int i = t; i < 64 * 64;  i += THREADS) w2s[i] = W2[i];
    if (t < 64) {
        w3s[t]  = W3[t];
        b1s[t]  = b1[t];  g1s[t] = g1[t];  be1s[t] = be1[t];
        b2s[t]  = b2[t];  g2s[t] = g2[t];  be2s[t] = be2[t];
    }
    const float b3v = b3[0];
    __syncthreads();

    const int tx = t & 15;          // output-column group
    const int ty = t >> 4;          // edge-row group
    const int e0 = ty * 4;
    const int j0 = tx * 4;
    const int el = t >> 2;          // LN phase: edge handled by this thread
    const int sub = t & 3;          // LN phase: quarter of the 64-dim row

    const int ntiles = (E + TILE_E - 1) / TILE_E;
    for (int tile = blockIdx.x; tile < ntiles; tile += gridDim.x) {
        const int ebase = tile * TILE_E;

        // ---------- gather: build xs[k][e], k in [0,144) ----------
        {
            const int ge = ebase + el;
            if (ge < E) {
                const long long s = (long long)eidx[ge];
                const long long d = (long long)eidx[E + ge];
                const float4* srow = (const float4*)(nf + s * 64);
                const float4* drow = (const float4*)(nf + d * 64);
                #pragma unroll
                for (int i = 0; i < 4; i++) {
                    float4 v = srow[sub * 4 + i];
                    int k = sub * 16 + i * 4;
                    xs[(k + 0) * EPAD + el] = v.x;
                    xs[(k + 1) * EPAD + el] = v.y;
                    xs[(k + 2) * EPAD + el] = v.z;
                    xs[(k + 3) * EPAD + el] = v.w;
                }
                #pragma unroll
                for (int i = 0; i < 4; i++) {
                    float4 v = drow[sub * 4 + i];
                    int k = 64 + sub * 16 + i * 4;
                    xs[(k + 0) * EPAD + el] = v.x;
                    xs[(k + 1) * EPAD + el] = v.y;
                    xs[(k + 2) * EPAD + el] = v.z;
                    xs[(k + 3) * EPAD + el] = v.w;
                }
                {
                    float4 v = ((const float4*)(eattr + (long long)ge * 16))[sub];
                    int k = 128 + sub * 4;
                    xs[(k + 0) * EPAD + el] = v.x;
                    xs[(k + 1) * EPAD + el] = v.y;
                    xs[(k + 2) * EPAD + el] = v.z;
                    xs[(k + 3) * EPAD + el] = v.w;
                }
            } else {
                for (int k = sub; k < 144; k += 4) xs[k * EPAD + el] = 0.0f;
            }
        }
        __syncthreads();

        // ---------- GEMM1: h = x @ W1  (per-thread 4 edges x 4 cols) ----------
        float c[16];
        #pragma unroll
        for (int i = 0; i < 16; i++) c[i] = 0.0f;
        {
            const float* xp = xs + e0;
            const float* wp = w1s + j0;
            #pragma unroll 4
            for (int k = 0; k < 144; k++) {
                float4 a = *(const float4*)(xp + k * EPAD);
                float4 b = *(const float4*)(wp + k * 64);
                c[0]  += a.x * b.x; c[1]  += a.x * b.y; c[2]  += a.x * b.z; c[3]  += a.x * b.w;
                c[4]  += a.y * b.x; c[5]  += a.y * b.y; c[6]  += a.y * b.z; c[7]  += a.y * b.w;
                c[8]  += a.z * b.x; c[9]  += a.z * b.y; c[10] += a.z * b.z; c[11] += a.z * b.w;
                c[12] += a.w * b.x; c[13] += a.w * b.y; c[14] += a.w * b.z; c[15] += a.w * b.w;
            }
        }
        __syncthreads();   // all reads of xs done before hs(=xs) is overwritten

        {
            float4 bb = *(const float4*)(b1s + j0);
            #pragma unroll
            for (int i = 0; i < 4; i++) {
                float4 st;
                st.x = c[i * 4 + 0] + bb.x;
                st.y = c[i * 4 + 1] + bb.y;
                st.z = c[i * 4 + 2] + bb.z;
                st.w = c[i * 4 + 3] + bb.w;
                *(float4*)(hs + (e0 + i) * EPAD + j0) = st;
            }
        }
        __syncthreads();

        // ---------- LN1 + leaky -> x2s[j][e] (transposed) ----------
        {
            const float* hrow = hs + el * EPAD + sub * 16;
            float v[16];
            float s = 0.0f, sq = 0.0f;
            #pragma unroll
            for (int i = 0; i < 4; i++) {
                float4 q = *(const float4*)(hrow + i * 4);
                v[i * 4 + 0] = q.x; v[i * 4 + 1] = q.y;
                v[i * 4 + 2] = q.z; v[i * 4 + 3] = q.w;
            }
            #pragma unroll
            for (int i = 0; i < 16; i++) { s += v[i]; sq += v[i] * v[i]; }
            s  += __shfl_xor_sync(0xffffffffu, s, 1);
            sq += __shfl_xor_sync(0xffffffffu, sq, 1);
            s  += __shfl_xor_sync(0xffffffffu, s, 2);
            sq += __shfl_xor_sync(0xffffffffu, sq, 2);
            const float mu = s * (1.0f / 64.0f);
            float var = sq * (1.0f / 64.0f) - mu * mu;
            const float rstd = rsqrtf(var + 1e-5f);
            #pragma unroll
            for (int i = 0; i < 16; i++) {
                int j = sub * 16 + i;
                float y = (v[i] - mu) * rstd * g1s[j] + be1s[j];
                y = (y >= 0.0f) ? y : 0.1f * y;
                x2s[j * EPAD + el] = y;
            }
        }
        __syncthreads();

        // ---------- GEMM2: h2 = h1 @ W2 ----------
        #pragma unroll
        for (int i = 0; i < 16; i++) c[i] = 0.0f;
        {
            const float* xp = x2s + e0;
            const float* wp = w2s + j0;
            #pragma unroll 4
            for (int k = 0; k < 64; k++) {
                float4 a = *(const float4*)(xp + k * EPAD);
                float4 b = *(const float4*)(wp + k * 64);
                c[0]  += a.x * b.x; c[1]  += a.x * b.y; c[2]  += a.x * b.z; c[3]  += a.x * b.w;
                c[4]  += a.y * b.x; c[5]  += a.y * b.y; c[6]  += a.y * b.z; c[7]  += a.y * b.w;
                c[8]  += a.z * b.x; c[9]  += a.z * b.y; c[10] += a.z * b.z; c[11] += a.z * b.w;
                c[12] += a.w * b.x; c[13] += a.w * b.y; c[14] += a.w * b.z; c[15] += a.w * b.w;
            }
        }
        {
            float4 bb = *(const float4*)(b2s + j0);
            #pragma unroll
            for (int i = 0; i < 4; i++) {
                float4 st;
                st.x = c[i * 4 + 0] + bb.x;
                st.y = c[i * 4 + 1] + bb.y;
                st.z = c[i * 4 + 2] + bb.z;
                st.w = c[i * 4 + 3] + bb.w;
                *(float4*)(hs + (e0 + i) * EPAD + j0) = st;   // hs region, disjoint from x2s
            }
        }
        __syncthreads();

        // ---------- LN2 + leaky + dot(W3) -> out ----------
        {
            const float* hrow = hs + el * EPAD + sub * 16;
            float v[16];
            float s = 0.0f, sq = 0.0f;
            #pragma unroll
            for (int i = 0; i < 4; i++) {
                float4 q = *(const float4*)(hrow + i * 4);
                v[i * 4 + 0] = q.x; v[i * 4 + 1] = q.y;
                v[i * 4 + 2] = q.z; v[i * 4 + 3] = q.w;
            }
            #pragma unroll
            for (int i = 0; i < 16; i++) { s += v[i]; sq += v[i] * v[i]; }
            s  += __shfl_xor_sync(0xffffffffu, s, 1);
            sq += __shfl_xor_sync(0xffffffffu, sq, 1);
            s  += __shfl_xor_sync(0xffffffffu, s, 2);
            sq += __shfl_xor_sync(0xffffffffu, sq, 2);
            const float mu = s * (1.0f / 64.0f);
            float var = sq * (1.0f / 64.0f) - mu * mu;
            const float rstd = rsqrtf(var + 1e-5f);
            float acc = 0.0f;
            #pragma unroll
            for (int i = 0; i < 16; i++) {
                int j = sub * 16 + i;
                float y = (v[i] - mu) * rstd * g2s[j] + be2s[j];
                y = (y >= 0.0f) ? y : 0.1f * y;
                acc += y * w3s[j];
            }
            acc += __shfl_xor_sync(0xffffffffu, acc, 1);
            acc += __shfl_xor_sync(0xffffffffu, acc, 2);
            if (sub == 0 && (ebase + el) < E)
                out[ebase + el] = acc + b3v;
        }
        __syncthreads();   // before next tile's gather overwrites xs/hs
    }
}

extern "C" void kernel_launch(void* const* d_in, const int* in_sizes, int n_in,
                              void* d_out, int out_size) {
    const float* nf    = (const float*)d_in[0];
    const int*   eidx  = (const int*)d_in[1];
    const float* eattr = (const float*)d_in[2];
    const float* W1 = (const float*)d_in[3];
    const float* b1 = (const float*)d_in[4];
    const float* g1 = (const float*)d_in[5];
    const float* be1= (const float*)d_in[6];
    const float* W2 = (const float*)d_in[7];
    const float* b2 = (const float*)d_in[8];
    const float* g2 = (const float*)d_in[9];
    const float* be2= (const float*)d_in[10];
    const float* W3 = (const float*)d_in[11];
    const float* b3 = (const float*)d_in[12];
    float* out = (float*)d_out;
    const int E = out_size;

    cudaFuncSetAttribute(edge_mlp_kernel,
                         cudaFuncAttributeMaxDynamicSharedMemorySize,
                         SMEM_FLOATS * sizeof(float));

    int ntiles = (E + TILE_E - 1) / TILE_E;
    int grid = ntiles < 296 ? ntiles : 296;   // persistent blocks, 2/SM on 148 SMs
    edge_mlp_kernel<<<grid, THREADS, SMEM_FLOATS * sizeof(float)>>>(
        nf, eidx, eattr, W1, b1, g1, be1, W2, b2, g2, be2, W3, b3, out, E);
}